// round 2
// baseline (speedup 1.0000x reference)
#include <cuda_runtime.h>
#include <math.h>

#define NB      8192
#define ND      512
#define NK      8
#define THREADS 256
#define WARPS   (THREADS / 32)
#define FULL    0xffffffffu

__device__ double g_acc;

__global__ void nest_zero_kernel() { g_acc = 0.0; }

__global__ void __launch_bounds__(THREADS) nest_main_kernel(
    const float* __restrict__ S,   // [NB, ND]
    const float* __restrict__ L)   // [NB]
{
    __shared__ float sL[NB];       // 32 KB

    const int tid  = threadIdx.x;
    const int wid  = tid >> 5;
    const int lane = tid & 31;

    // Stage all labels in shared memory (cooperative, coalesced)
    for (int i = tid; i < NB; i += THREADS) sL[i] = L[i];
    __syncthreads();

    const int b  = blockIdx.x * WARPS + wid;   // one warp per row
    const float Lb = sL[b];

    // -------- Phase 1: lane-local top-8 smallest |sL[c] - Lb| --------
    float dd_[NK];
    int   id_[NK];
#pragma unroll
    for (int k = 0; k < NK; k++) { dd_[k] = INFINITY; id_[k] = 0; }

    for (int c = lane; c < NB; c += 32) {
        float t = fabsf(sL[c] - Lb);
        if (t < dd_[NK - 1]) {
            dd_[NK - 1] = t; id_[NK - 1] = c;
            // one bubble pass restores ascending order
#pragma unroll
            for (int k = NK - 1; k > 0; k--) {
                if (dd_[k] < dd_[k - 1]) {
                    float tf = dd_[k]; dd_[k] = dd_[k - 1]; dd_[k - 1] = tf;
                    int   ti = id_[k]; id_[k] = id_[k - 1]; id_[k - 1] = ti;
                }
            }
        }
    }

    // -------- Phase 2: warp merge -> global top-8 + Gaussian weights --------
    int   gidx[NK];
    float w[NK];
    float wsum = 0.0f;

#pragma unroll
    for (int r = 0; r < NK; r++) {
        // candidate = each lane's current smallest (dd_[0]); find warp min
        unsigned bk = __float_as_uint(dd_[0]);  // dd >= 0 -> uint order == float order
        int      bl = lane;
#pragma unroll
        for (int off = 16; off > 0; off >>= 1) {
            unsigned ok = __shfl_xor_sync(FULL, bk, off);
            int      ol = __shfl_xor_sync(FULL, bl, off);
            if (ok < bk || (ok == bk && ol < bl)) { bk = ok; bl = ol; }
        }
        int gi = __shfl_sync(FULL, id_[0], bl);
        gidx[r] = gi;

        float dist = __uint_as_float(bk);
        // unnormalized gaussian: the 1/(sqrt(2pi)*std) prefactor cancels
        float e = expf(-(dist * dist) * (1.0f / 50.0f));   // 2*STD^2 = 50
        w[r] = e;
        wsum += e;

        // pop from winning lane's list
        if (lane == bl) {
#pragma unroll
            for (int k = 0; k < NK - 1; k++) { dd_[k] = dd_[k + 1]; id_[k] = id_[k + 1]; }
            dd_[NK - 1] = INFINITY;
        }
    }

    float winv = 1.0f / wsum;
#pragma unroll
    for (int r = 0; r < NK; r++) w[r] *= winv;

    // -------- Phase 3: fused gather + weighted mean + cosine terms --------
    const float4* xr = (const float4*)(S + (size_t)b * ND);
    float dot = 0.0f, nx = 0.0f, nm = 0.0f;

#pragma unroll
    for (int t = 0; t < (ND / 4) / 32; t++) {     // 4 iterations
        int col = lane + t * 32;
        float4 x = xr[col];
        float mx = 0.0f, my = 0.0f, mz = 0.0f, mw = 0.0f;
#pragma unroll
        for (int r = 0; r < NK; r++) {
            float4 s = ((const float4*)(S + (size_t)gidx[r] * ND))[col];
            mx = fmaf(w[r], s.x, mx);
            my = fmaf(w[r], s.y, my);
            mz = fmaf(w[r], s.z, mz);
            mw = fmaf(w[r], s.w, mw);
        }
        dot += x.x * mx + x.y * my + x.z * mz + x.w * mw;
        nx  += x.x * x.x + x.y * x.y + x.z * x.z + x.w * x.w;
        nm  += mx * mx + my * my + mz * mz + mw * mw;
    }

    // warp reduce the three sums
#pragma unroll
    for (int off = 16; off > 0; off >>= 1) {
        dot += __shfl_xor_sync(FULL, dot, off);
        nx  += __shfl_xor_sync(FULL, nx,  off);
        nm  += __shfl_xor_sync(FULL, nm,  off);
    }

    if (lane == 0) {
        float sim = dot / ((1e-10f + sqrtf(nx)) * (1e-10f + sqrtf(nm)));
        atomicAdd(&g_acc, (double)sim);
    }
}

__global__ void nest_fin_kernel(float* __restrict__ out) {
    out[0] = (float)(1.0 - g_acc / (double)NB);
}

extern "C" void kernel_launch(void* const* d_in, const int* in_sizes, int n_in,
                              void* d_out, int out_size)
{
    const float* S = (const float*)d_in[0];   // Struct [8192, 512]
    const float* L = (const float*)d_in[1];   // Label  [8192]
    float* out = (float*)d_out;

    nest_zero_kernel<<<1, 1>>>();
    nest_main_kernel<<<NB / WARPS, THREADS>>>(S, L);
    nest_fin_kernel<<<1, 1>>>(out);
}

// round 5
// speedup vs baseline: 2.2505x; 2.2505x over previous
#include <cuda_runtime.h>
#include <math.h>

#define NB      8192
#define ND      512
#define NK      8
#define FULL    0xffffffffu

__device__ double g_acc;
__device__ float  g_slab[NB];   // labels in sorted order
__device__ int    g_sidx[NB];   // original row index per sorted position

__global__ void nest_zero_kernel() { g_acc = 0.0; }

// ---------------- Rank kernel: warp per row, branch-free counting rank ------
#define RT 512
#define RW (RT / 32)
__global__ void __launch_bounds__(RT) nest_rank_kernel(const float* __restrict__ L)
{
    __shared__ unsigned long long sK[NB];   // 64 KB

    const int tid  = threadIdx.x;
    const int wid  = tid >> 5;
    const int lane = tid & 31;

    for (int i = tid; i < NB; i += RT)
        sK[i] = ((unsigned long long)__float_as_uint(L[i]) << 13) | (unsigned)i;
    __syncthreads();

    const int b = blockIdx.x * RW + wid;
    const unsigned long long kb = sK[b];

    int r = 0;
#pragma unroll 8
    for (int c = lane; c < NB; c += 32)
        r += (sK[c] < kb);

#pragma unroll
    for (int off = 16; off > 0; off >>= 1)
        r += __shfl_xor_sync(FULL, r, off);

    if (lane == 0) {
        g_slab[r] = __uint_as_float((unsigned)(kb >> 13));
        g_sidx[r] = b;
    }
}

// ------------- Main kernel: warp per sorted position, window select + gather -
#define THREADS 256
#define WARPS   (THREADS / 32)
__global__ void __launch_bounds__(THREADS) nest_main_kernel(const float* __restrict__ S)
{
    const int tid  = threadIdx.x;
    const int wid  = tid >> 5;
    const int lane = tid & 31;

    const int r  = blockIdx.x * WARPS + wid;    // sorted position
    const float Lb = g_slab[r];
    const int   b  = g_sidx[r];                 // original row

    // --- two-pointer nearest-8 over the sorted window (all lanes redundant,
    //     identical broadcast loads) ---
    int   gidx[NK];
    float w[NK];
    gidx[0] = b; w[0] = 1.0f;                   // self: dist 0, exp(0)=1
    float wsum = 1.0f;

    int lo = r - 1, hi = r + 1;
#pragma unroll
    for (int k = 1; k < NK; k++) {
        float dl = (lo >= 0) ? Lb - g_slab[lo] : INFINITY;
        float dh = (hi < NB) ? g_slab[hi] - Lb : INFINITY;
        float d; int gi;
        if (dl <= dh) { gi = g_sidx[lo]; d = dl; lo--; }
        else          { gi = g_sidx[hi]; d = dh; hi++; }
        gidx[k] = gi;
        float e = __expf(-d * d * (1.0f / 50.0f));   // 2*STD^2 = 50; prefactor cancels
        w[k] = e; wsum += e;
    }

    const float winv = 1.0f / wsum;
#pragma unroll
    for (int k = 0; k < NK; k++) w[k] *= winv;

    // --- fused gather + weighted mean + cosine terms ---
    const float4* xr = (const float4*)(S + (size_t)b * ND);
    float dot = 0.0f, nx = 0.0f, nm = 0.0f;

#pragma unroll
    for (int t = 0; t < (ND / 4) / 32; t++) {   // 4 iterations
        int col = lane + t * 32;
        float4 x = xr[col];
        float mx = 0.0f, my = 0.0f, mz = 0.0f, mw = 0.0f;
#pragma unroll
        for (int k = 0; k < NK; k++) {
            float4 s = ((const float4*)(S + (size_t)gidx[k] * ND))[col];
            mx = fmaf(w[k], s.x, mx);
            my = fmaf(w[k], s.y, my);
            mz = fmaf(w[k], s.z, mz);
            mw = fmaf(w[k], s.w, mw);
        }
        dot += x.x * mx + x.y * my + x.z * mz + x.w * mw;
        nx  += x.x * x.x + x.y * x.y + x.z * x.z + x.w * x.w;
        nm  += mx * mx + my * my + mz * mz + mw * mw;
    }

#pragma unroll
    for (int off = 16; off > 0; off >>= 1) {
        dot += __shfl_xor_sync(FULL, dot, off);
        nx  += __shfl_xor_sync(FULL, nx,  off);
        nm  += __shfl_xor_sync(FULL, nm,  off);
    }

    if (lane == 0) {
        float sim = dot / ((1e-10f + sqrtf(nx)) * (1e-10f + sqrtf(nm)));
        atomicAdd(&g_acc, (double)sim);
    }
}

__global__ void nest_fin_kernel(float* __restrict__ out) {
    out[0] = (float)(1.0 - g_acc / (double)NB);
}

extern "C" void kernel_launch(void* const* d_in, const int* in_sizes, int n_in,
                              void* d_out, int out_size)
{
    const float* S = (const float*)d_in[0];   // Struct [8192, 512]
    const float* L = (const float*)d_in[1];   // Label  [8192]
    float* out = (float*)d_out;

    nest_zero_kernel<<<1, 1>>>();
    nest_rank_kernel<<<NB / RW, RT>>>(L);
    nest_main_kernel<<<NB / WARPS, THREADS>>>(S);
    nest_fin_kernel<<<1, 1>>>(out);
}

// round 7
// speedup vs baseline: 3.9217x; 1.7426x over previous
#include <cuda_runtime.h>
#include <math.h>

#define NB      8192
#define ND      512
#define NK      8
#define FULL    0xffffffffu

#define THREADS 256
#define WARPS   (THREADS / 32)
#define NBLK    (NB / WARPS)

__device__ double g_acc;
__device__ int    g_done = 0;
__device__ float  g_slab[NB];   // labels in sorted order
__device__ int    g_sidx[NB];   // original row index per sorted position

// ---------------- Rank kernel: warp per row, branch-free counting rank ------
// 32-bit keys (labels are uniform [0,1) -> nonneg floats, uint order == float
// order). Ties broken by original index so the scatter is a permutation.
#define RT 512
#define RW (RT / 32)
__global__ void __launch_bounds__(RT) nest_rank_kernel(const float* __restrict__ L)
{
    __shared__ unsigned sK[NB];   // 32 KB

    const int tid  = threadIdx.x;
    const int wid  = tid >> 5;
    const int lane = tid & 31;

    if (blockIdx.x == 0 && tid == 0) g_acc = 0.0;   // fused zeroing

    for (int i = tid; i < NB; i += RT)
        sK[i] = __float_as_uint(L[i]);
    __syncthreads();

    const int b = blockIdx.x * RW + wid;
    const unsigned kb = sK[b];

    int r = 0;
#pragma unroll 8
    for (int c = lane; c < NB; c += 32) {
        unsigned k = sK[c];
        r += (k < kb) | ((k == kb) & (c < b));
    }

#pragma unroll
    for (int off = 16; off > 0; off >>= 1)
        r += __shfl_xor_sync(FULL, r, off);

    if (lane == 0) {
        g_slab[r] = __uint_as_float(kb);
        g_sidx[r] = b;
    }
}

// ------------- Main kernel: warp per sorted position, window select + gather,
//               block-reduced sim, last-block finalize -----------------------
__global__ void __launch_bounds__(THREADS) nest_main_kernel(
    const float* __restrict__ S, float* __restrict__ out)
{
    __shared__ double sSim[WARPS];

    const int tid  = threadIdx.x;
    const int wid  = tid >> 5;
    const int lane = tid & 31;

    const int r  = blockIdx.x * WARPS + wid;    // sorted position
    const float Lb = g_slab[r];
    const int   b  = g_sidx[r];                 // original row

    // --- two-pointer nearest-8 over the sorted window (broadcast loads) ---
    int   gidx[NK];
    float w[NK];
    gidx[0] = b; w[0] = 1.0f;                   // self: dist 0
    float wsum = 1.0f;

    int lo = r - 1, hi = r + 1;
#pragma unroll
    for (int k = 1; k < NK; k++) {
        float dl = (lo >= 0) ? Lb - g_slab[lo] : INFINITY;
        float dh = (hi < NB) ? g_slab[hi] - Lb : INFINITY;
        float d; int gi;
        if (dl <= dh) { gi = g_sidx[lo]; d = dl; lo--; }
        else          { gi = g_sidx[hi]; d = dh; hi++; }
        gidx[k] = gi;
        float e = __expf(-d * d * (1.0f / 50.0f));   // 2*STD^2 = 50
        w[k] = e; wsum += e;
    }

    const float winv = 1.0f / wsum;
#pragma unroll
    for (int k = 0; k < NK; k++) w[k] *= winv;

    // --- fused gather + weighted mean + cosine terms ---
    const float4* xr = (const float4*)(S + (size_t)b * ND);
    float dot = 0.0f, nx = 0.0f, nm = 0.0f;

#pragma unroll
    for (int t = 0; t < (ND / 4) / 32; t++) {   // 4 iterations
        int col = lane + t * 32;
        float4 x = xr[col];
        float mx = 0.0f, my = 0.0f, mz = 0.0f, mw = 0.0f;
#pragma unroll
        for (int k = 0; k < NK; k++) {
            float4 s = ((const float4*)(S + (size_t)gidx[k] * ND))[col];
            mx = fmaf(w[k], s.x, mx);
            my = fmaf(w[k], s.y, my);
            mz = fmaf(w[k], s.z, mz);
            mw = fmaf(w[k], s.w, mw);
        }
        dot += x.x * mx + x.y * my + x.z * mz + x.w * mw;
        nx  += x.x * x.x + x.y * x.y + x.z * x.z + x.w * x.w;
        nm  += mx * mx + my * my + mz * mz + mw * mw;
    }

#pragma unroll
    for (int off = 16; off > 0; off >>= 1) {
        dot += __shfl_xor_sync(FULL, dot, off);
        nx  += __shfl_xor_sync(FULL, nx,  off);
        nm  += __shfl_xor_sync(FULL, nm,  off);
    }

    if (lane == 0) {
        float sim = dot / ((1e-10f + sqrtf(nx)) * (1e-10f + sqrtf(nm)));
        sSim[wid] = (double)sim;
    }
    __syncthreads();

    if (tid == 0) {
        double bs = 0.0;
#pragma unroll
        for (int k = 0; k < WARPS; k++) bs += sSim[k];
        atomicAdd(&g_acc, bs);                  // 1 atomic per block
        __threadfence();
        int old = atomicAdd(&g_done, 1);
        if (old == NBLK - 1) {                  // last block finalizes
            double total = *((volatile double*)&g_acc);
            out[0] = (float)(1.0 - total / (double)NB);
            g_done = 0;                         // reset for next graph replay
        }
    }
}

extern "C" void kernel_launch(void* const* d_in, const int* in_sizes, int n_in,
                              void* d_out, int out_size)
{
    const float* S = (const float*)d_in[0];   // Struct [8192, 512]
    const float* L = (const float*)d_in[1];   // Label  [8192]
    float* out = (float*)d_out;

    nest_rank_kernel<<<NB / RW, RT>>>(L);
    nest_main_kernel<<<NBLK, THREADS>>>(S, out);
}

// round 8
// speedup vs baseline: 4.4323x; 1.1302x over previous
#include <cuda_runtime.h>
#include <math.h>

#define NB      8192
#define ND      512
#define NK      8
#define FULL    0xffffffffu

#define THREADS 256
#define WARPS   (THREADS / 32)
#define NBLK    (NB / WARPS)

__device__ double g_acc;
__device__ int    g_done = 0;
__device__ float  g_slab[NB];   // labels in sorted order
__device__ int    g_sidx[NB];   // original row index per sorted position

// ---------------- Rank kernel: warp per 8 rows, branch-free counting rank ---
// 64-bit packed keys (label_bits<<13 | idx): labels are nonneg floats so uint
// order == float order; idx in the low bits makes keys unique -> the scatter
// is an exact permutation with a single u64 compare (no separate tie-break).
#define RT     128
#define RROWS  8                       // rows ranked per warp
#define RWARPS (RT / 32)
#define RBLK   (NB / (RROWS * RWARPS)) // 256 blocks

__global__ void __launch_bounds__(RT) nest_rank_kernel(const float* __restrict__ L)
{
    __shared__ unsigned long long sK[NB];   // 64 KB

    const int tid  = threadIdx.x;
    const int wid  = tid >> 5;
    const int lane = tid & 31;

    if (blockIdx.x == 0 && tid == 0) g_acc = 0.0;   // fused zeroing

    for (int i = tid; i < NB; i += RT)
        sK[i] = ((unsigned long long)__float_as_uint(L[i]) << 13) | (unsigned)i;
    __syncthreads();

    const int base = (blockIdx.x * RWARPS + wid) * RROWS;

    unsigned long long kb[RROWS];
    int r[RROWS];
#pragma unroll
    for (int j = 0; j < RROWS; j++) { kb[j] = sK[base + j]; r[j] = 0; }

#pragma unroll 4
    for (int c = lane; c < NB; c += 32) {
        unsigned long long k = sK[c];
#pragma unroll
        for (int j = 0; j < RROWS; j++)
            r[j] += (k < kb[j]);
    }

#pragma unroll
    for (int j = 0; j < RROWS; j++) {
#pragma unroll
        for (int off = 16; off > 0; off >>= 1)
            r[j] += __shfl_xor_sync(FULL, r[j], off);
    }

    if (lane == 0) {
#pragma unroll
        for (int j = 0; j < RROWS; j++) {
            g_slab[r[j]] = __uint_as_float((unsigned)(kb[j] >> 13));
            g_sidx[r[j]] = base + j;
        }
    }
}

// ------------- Main kernel: warp per sorted position, window select + gather,
//               block-reduced sim, last-block finalize -----------------------
__global__ void __launch_bounds__(THREADS) nest_main_kernel(
    const float* __restrict__ S, float* __restrict__ out)
{
    __shared__ double sSim[WARPS];

    const int tid  = threadIdx.x;
    const int wid  = tid >> 5;
    const int lane = tid & 31;

    const int r  = blockIdx.x * WARPS + wid;    // sorted position
    const float Lb = g_slab[r];
    const int   b  = g_sidx[r];                 // original row

    // --- two-pointer nearest-8 over the sorted window (broadcast loads) ---
    int   gidx[NK];
    float w[NK];
    gidx[0] = b; w[0] = 1.0f;                   // self: dist 0
    float wsum = 1.0f;

    int lo = r - 1, hi = r + 1;
#pragma unroll
    for (int k = 1; k < NK; k++) {
        float dl = (lo >= 0) ? Lb - g_slab[lo] : INFINITY;
        float dh = (hi < NB) ? g_slab[hi] - Lb : INFINITY;
        float d; int gi;
        if (dl <= dh) { gi = g_sidx[lo]; d = dl; lo--; }
        else          { gi = g_sidx[hi]; d = dh; hi++; }
        gidx[k] = gi;
        float e = __expf(-d * d * (1.0f / 50.0f));   // 2*STD^2 = 50
        w[k] = e; wsum += e;
    }

    const float winv = 1.0f / wsum;
#pragma unroll
    for (int k = 0; k < NK; k++) w[k] *= winv;

    // --- fused gather + weighted mean + cosine terms ---
    // front-load all 4 self-row tiles (16 independent LDG.128) for MLP
    const float4* xr = (const float4*)(S + (size_t)b * ND);
    float4 x[4];
#pragma unroll
    for (int t = 0; t < 4; t++) x[t] = xr[lane + t * 32];

    float dot = 0.0f, nx = 0.0f, nm = 0.0f;

#pragma unroll
    for (int t = 0; t < 4; t++) {
        int col = lane + t * 32;
        float mx = 0.0f, my = 0.0f, mz = 0.0f, mw = 0.0f;
#pragma unroll
        for (int k = 0; k < NK; k++) {
            float4 s = ((const float4*)(S + (size_t)gidx[k] * ND))[col];
            mx = fmaf(w[k], s.x, mx);
            my = fmaf(w[k], s.y, my);
            mz = fmaf(w[k], s.z, mz);
            mw = fmaf(w[k], s.w, mw);
        }
        dot += x[t].x * mx + x[t].y * my + x[t].z * mz + x[t].w * mw;
        nx  += x[t].x * x[t].x + x[t].y * x[t].y + x[t].z * x[t].z + x[t].w * x[t].w;
        nm  += mx * mx + my * my + mz * mz + mw * mw;
    }

#pragma unroll
    for (int off = 16; off > 0; off >>= 1) {
        dot += __shfl_xor_sync(FULL, dot, off);
        nx  += __shfl_xor_sync(FULL, nx,  off);
        nm  += __shfl_xor_sync(FULL, nm,  off);
    }

    if (lane == 0) {
        float sim = dot / ((1e-10f + sqrtf(nx)) * (1e-10f + sqrtf(nm)));
        sSim[wid] = (double)sim;
    }
    __syncthreads();

    if (tid == 0) {
        double bs = 0.0;
#pragma unroll
        for (int k = 0; k < WARPS; k++) bs += sSim[k];
        atomicAdd(&g_acc, bs);                  // 1 atomic per block
        __threadfence();
        int old = atomicAdd(&g_done, 1);
        if (old == NBLK - 1) {                  // last block finalizes
            double total = *((volatile double*)&g_acc);
            out[0] = (float)(1.0 - total / (double)NB);
            g_done = 0;                         // reset for next graph replay
        }
    }
}

extern "C" void kernel_launch(void* const* d_in, const int* in_sizes, int n_in,
                              void* d_out, int out_size)
{
    const float* S = (const float*)d_in[0];   // Struct [8192, 512]
    const float* L = (const float*)d_in[1];   // Label  [8192]
    float* out = (float*)d_out;

    nest_rank_kernel<<<RBLK, RT>>>(L);
    nest_main_kernel<<<NBLK, THREADS>>>(S, out);
}